// round 8
// baseline (speedup 1.0000x reference)
#include <cuda_runtime.h>
#include <cuda_fp16.h>
#include <cuda_bf16.h>

#define NN 20000
#define EE 320000
#define HH 8
#define DD 32
#define F1 128
#define HD 256   // H*D
#define TRB 64   // gemm row tile

// ---------------- scratch (device globals; no allocation allowed) -------------
__device__ __half g_feat[NN * HD];     // layer-1 feat [N, dim*8+head] fp16
__device__ __half g_feat2[NN * HD];    // layer-2 feat (separate: layer-1 is read globally)
__device__ float g_el[NN * HH];
__device__ float g_er[NN * HH];
__device__ float g_el2[NN * HH];
__device__ float g_er2[NN * HH];
__device__ float g_Wp1[F1 * HD];       // tf32 bits, permuted cols
__device__ float g_Wp2[DD * HD];
__device__ float g_alp1[HD], g_arp1[HD];
__device__ float g_alp2[HD], g_arp2[HD];
__device__ int   g_cnt[NN];            // INVARIANT: zero on entry to every call
__device__ int   g_rowptr[NN + 1];
__device__ int   g_fill[NN];
__device__ int   g_esrc[EE];

__device__ __forceinline__ unsigned f2tf32(float f) {
    unsigned u;
    asm("cvt.rna.tf32.f32 %0, %1;" : "=r"(u) : "f"(f));
    return u;
}

__device__ __forceinline__ void mma_tf32(float& d0, float& d1, float& d2, float& d3,
                                         unsigned a0, unsigned a1, unsigned a2, unsigned a3,
                                         unsigned b0, unsigned b1) {
    asm volatile("mma.sync.aligned.m16n8k8.row.col.f32.tf32.tf32.f32 "
                 "{%0,%1,%2,%3}, {%4,%5,%6,%7}, {%8,%9}, {%0,%1,%2,%3};"
                 : "+f"(d0), "+f"(d1), "+f"(d2), "+f"(d3)
                 : "r"(a0), "r"(a1), "r"(a2), "r"(a3), "r"(b0), "r"(b1));
}

// ---------------- weight permutation + tf32 conversion ------------------------
__global__ void perm_kernel(const float* __restrict__ W1,
                            const float* __restrict__ al1,
                            const float* __restrict__ ar1,
                            const float* __restrict__ W2,
                            const float* __restrict__ al2,
                            const float* __restrict__ ar2) {
    int t = blockIdx.x * 256 + threadIdx.x;
    if (t < F1 * HD) {
        int k = t >> 8, j = t & 255;
        int L = ((j & 7) << 5) | (j >> 3);
        g_Wp1[t] = __uint_as_float(f2tf32(W1[k * HD + L]));
    }
    if (t < DD * HD) {
        int k = t >> 8, j = t & 255;
        int L = ((j & 7) << 5) | (j >> 3);
        g_Wp2[t] = __uint_as_float(f2tf32(W2[k * HD + L]));
    }
    if (t < HD) {
        int L = ((t & 7) << 5) | (t >> 3);
        g_alp1[t] = al1[L]; g_arp1[t] = ar1[L];
        g_alp2[t] = al2[L]; g_arp2[t] = ar2[L];
    }
}

// ---------------- CSR chain (runs on forked stream) ---------------------------
__global__ void hist_kernel(const int* __restrict__ dst) {
    int e = blockIdx.x * blockDim.x + threadIdx.x;
    if (e < EE) atomicAdd(&g_cnt[dst[e]], 1);
}

__global__ void scan_kernel() {   // also restores g_cnt = 0 invariant
    __shared__ int ssum[1024];
    int t = threadIdx.x;
    const int chunk = (NN + 1023) / 1024;
    int b = t * chunk, e = min(b + chunk, NN);
    int s = 0;
    for (int i = b; i < e; i++) s += g_cnt[i];
    ssum[t] = s;
    __syncthreads();
    for (int off = 1; off < 1024; off <<= 1) {
        int v = (t >= off) ? ssum[t - off] : 0;
        __syncthreads();
        ssum[t] += v;
        __syncthreads();
    }
    int pref = (t > 0) ? ssum[t - 1] : 0;
    for (int i = b; i < e; i++) {
        int c = g_cnt[i];
        g_rowptr[i] = pref;
        g_fill[i]   = pref;
        g_cnt[i]    = 0;
        pref += c;
    }
    if (t == 1023) g_rowptr[NN] = ssum[1023];
}

__global__ void scatter_kernel(const int* __restrict__ src,
                               const int* __restrict__ dst) {
    int e = blockIdx.x * blockDim.x + threadIdx.x;
    if (e < EE) {
        int p = atomicAdd(&g_fill[dst[e]], 1);
        g_esrc[p] = src[e];
    }
}

// ---------------- per-node aggregation (warp-collective), unroll x4 -----------
template <bool RELU>
__device__ __forceinline__ float agg_node(int node, int lane,
                                          const __half* __restrict__ feat,
                                          const float* __restrict__ el,
                                          const float* __restrict__ er,
                                          const float* __restrict__ bias) {
    int hh = lane & 7;
    float er_l = er[node * HH + hh];
    int beg = g_rowptr[node], end = g_rowptr[node + 1];

    float acc[8];
#pragma unroll
    for (int h = 0; h < 8; h++) acc[h] = 0.f;
    float den_l = 0.f;

    int i = beg;
    for (; i + 4 <= end; i += 4) {
        int s0 = g_esrc[i + 0], s1 = g_esrc[i + 1];
        int s2 = g_esrc[i + 2], s3 = g_esrc[i + 3];
        float el0 = __ldg(el + s0 * HH + hh);
        float el1 = __ldg(el + s1 * HH + hh);
        float el2 = __ldg(el + s2 * HH + hh);
        float el3 = __ldg(el + s3 * HH + hh);
        uint4 u0 = *(const uint4*)(&feat[(size_t)s0 * HD + lane * 8]);
        uint4 u1 = *(const uint4*)(&feat[(size_t)s1 * HD + lane * 8]);
        uint4 u2 = *(const uint4*)(&feat[(size_t)s2 * HD + lane * 8]);
        uint4 u3 = *(const uint4*)(&feat[(size_t)s3 * HD + lane * 8]);
        float v0 = el0 + er_l; v0 = v0 > 0.f ? v0 : 0.2f * v0;
        float v1 = el1 + er_l; v1 = v1 > 0.f ? v1 : 0.2f * v1;
        float v2 = el2 + er_l; v2 = v2 > 0.f ? v2 : 0.2f * v2;
        float v3 = el3 + er_l; v3 = v3 > 0.f ? v3 : 0.2f * v3;
        float e0 = __expf(v0), e1 = __expf(v1);
        float e2 = __expf(v2), e3 = __expf(v3);
        den_l += (e0 + e1) + (e2 + e3);
        const unsigned* p0 = &u0.x;
        const unsigned* p1 = &u1.x;
        const unsigned* p2 = &u2.x;
        const unsigned* p3 = &u3.x;
#pragma unroll
        for (int q = 0; q < 4; q++) {       // q = head pair (2q, 2q+1)
            float2 f0 = __half22float2(*(const __half2*)&p0[q]);
            float2 f1 = __half22float2(*(const __half2*)&p1[q]);
            float2 f2 = __half22float2(*(const __half2*)&p2[q]);
            float2 f3 = __half22float2(*(const __half2*)&p3[q]);
            float wa0 = __shfl_sync(0xffffffffu, e0, 2 * q);
            float wa1 = __shfl_sync(0xffffffffu, e0, 2 * q + 1);
            float wb0 = __shfl_sync(0xffffffffu, e1, 2 * q);
            float wb1 = __shfl_sync(0xffffffffu, e1, 2 * q + 1);
            float wc0 = __shfl_sync(0xffffffffu, e2, 2 * q);
            float wc1 = __shfl_sync(0xffffffffu, e2, 2 * q + 1);
            float wd0 = __shfl_sync(0xffffffffu, e3, 2 * q);
            float wd1 = __shfl_sync(0xffffffffu, e3, 2 * q + 1);
            acc[2 * q]     = fmaf(wa0, f0.x, acc[2 * q]);
            acc[2 * q + 1] = fmaf(wa1, f0.y, acc[2 * q + 1]);
            acc[2 * q]     = fmaf(wb0, f1.x, acc[2 * q]);
            acc[2 * q + 1] = fmaf(wb1, f1.y, acc[2 * q + 1]);
            acc[2 * q]     = fmaf(wc0, f2.x, acc[2 * q]);
            acc[2 * q + 1] = fmaf(wc1, f2.y, acc[2 * q + 1]);
            acc[2 * q]     = fmaf(wd0, f3.x, acc[2 * q]);
            acc[2 * q + 1] = fmaf(wd1, f3.y, acc[2 * q + 1]);
        }
    }
    for (; i < end; i++) {
        int s = g_esrc[i];
        float elv = __ldg(el + s * HH + hh);
        uint4 u0 = *(const uint4*)(&feat[(size_t)s * HD + lane * 8]);
        float v = elv + er_l; v = v > 0.f ? v : 0.2f * v;
        float e = __expf(v);
        den_l += e;
        const unsigned* p0 = &u0.x;
#pragma unroll
        for (int q = 0; q < 4; q++) {
            float2 f0 = __half22float2(*(const __half2*)&p0[q]);
            float w0 = __shfl_sync(0xffffffffu, e, 2 * q);
            float w1 = __shfl_sync(0xffffffffu, e, 2 * q + 1);
            acc[2 * q]     = fmaf(w0, f0.x, acc[2 * q]);
            acc[2 * q + 1] = fmaf(w1, f0.y, acc[2 * q + 1]);
        }
    }

    float sum = 0.f;
#pragma unroll
    for (int h = 0; h < 8; h++) {
        float dh = __shfl_sync(0xffffffffu, den_l, h);
        float r = (dh > 0.f) ? __fdividef(acc[h], dh) : 0.f;
        r += bias[h * DD + lane];
        if (RELU) r = fmaxf(r, 0.f);
        sum += r;
    }
    return sum * 0.125f;
}

// ---------------- layer-1 GEMM (tf32 MMA) + fused el/er + fp16 feat -----------
__global__ __launch_bounds__(256, 2) void gemm1_kernel(const float* __restrict__ X,
                                                       int n) {
    constexpr int K = F1;
    constexpr int KC = 64;
    constexpr int XP = K + 4;
    constexpr int WP = 264;
    constexpr int STP = 260;
    extern __shared__ float sh[];
    unsigned* Wsh = (unsigned*)sh;                  // [KC][WP]
    unsigned* Xsh = (unsigned*)(sh + KC * WP);      // [TRB][XP]
    int tid = threadIdx.x;
    int wid = tid >> 5, lane = tid & 31;
    int g = lane >> 2, tg = lane & 3;
    int warpM = wid >> 2, warpN = wid & 3;
    int nbase = warpN * 64;

    int r0 = blockIdx.x * TRB;
    int nr = min(TRB, n - r0);

    for (int idx = tid; idx < TRB * K; idx += 256) {
        int r = idx / K, c = idx % K;
        float v = (r < nr) ? X[(size_t)(r0 + r) * K + c] : 0.f;
        Xsh[r * XP + c] = f2tf32(v);
    }

    float acc[2][8][4];
#pragma unroll
    for (int m = 0; m < 2; m++)
#pragma unroll
        for (int t = 0; t < 8; t++)
#pragma unroll
            for (int c = 0; c < 4; c++) acc[m][t][c] = 0.f;

    const unsigned* WpU = (const unsigned*)g_Wp1;
    for (int kc = 0; kc < K; kc += KC) {
        __syncthreads();
        for (int idx = tid; idx < KC * HD; idx += 256) {
            int kk = idx >> 8, j = idx & 255;
            Wsh[kk * WP + j] = WpU[(kc + kk) * HD + j];
        }
        __syncthreads();
#pragma unroll
        for (int kk = 0; kk < KC; kk += 8) {
            int k0 = kc + kk;
            unsigned a[2][4];
#pragma unroll
            for (int m = 0; m < 2; m++) {
                int rb = warpM * 32 + m * 16;
                a[m][0] = Xsh[(rb + g) * XP + k0 + tg];
                a[m][1] = Xsh[(rb + g + 8) * XP + k0 + tg];
                a[m][2] = Xsh[(rb + g) * XP + k0 + tg + 4];
                a[m][3] = Xsh[(rb + g + 8) * XP + k0 + tg + 4];
            }
#pragma unroll
            for (int t = 0; t < 8; t++) {
                int ncol = nbase + t * 8 + g;
                unsigned b0 = Wsh[(kk + tg) * WP + ncol];
                unsigned b1 = Wsh[(kk + tg + 4) * WP + ncol];
                mma_tf32(acc[0][t][0], acc[0][t][1], acc[0][t][2], acc[0][t][3],
                         a[0][0], a[0][1], a[0][2], a[0][3], b0, b1);
                mma_tf32(acc[1][t][0], acc[1][t][1], acc[1][t][2], acc[1][t][3],
                         a[1][0], a[1][1], a[1][2], a[1][3], b0, b1);
            }
        }
    }

    __syncthreads();
    float* stage = sh;          // [TRB][STP]
#pragma unroll
    for (int m = 0; m < 2; m++) {
        int rb = warpM * 32 + m * 16;
#pragma unroll
        for (int t = 0; t < 8; t++) {
            int c = nbase + t * 8 + 2 * tg;
            *(float2*)&stage[(rb + g) * STP + c] =
                make_float2(acc[m][t][0], acc[m][t][1]);
            *(float2*)&stage[(rb + g + 8) * STP + c] =
                make_float2(acc[m][t][2], acc[m][t][3]);
        }
    }
    __syncthreads();

    for (int i = tid; i < nr * 32; i += 256) {
        int row = i >> 5, cg = i & 31;
        const float4* s4 = (const float4*)&stage[row * STP + cg * 8];
        float4 f0 = s4[0], f1 = s4[1];
        __half2 h0 = __floats2half2_rn(f0.x, f0.y);
        __half2 h1 = __floats2half2_rn(f0.z, f0.w);
        __half2 h2 = __floats2half2_rn(f1.x, f1.y);
        __half2 h3 = __floats2half2_rn(f1.z, f1.w);
        uint4 u = make_uint4(*(unsigned*)&h0, *(unsigned*)&h1,
                             *(unsigned*)&h2, *(unsigned*)&h3);
        *(uint4*)(&g_feat[(size_t)(r0 + row) * HD + cg * 8]) = u;
    }

    float av[8], bv[8];
    {
        const float4* ap = (const float4*)(g_alp1 + lane * 8);
        const float4* bp = (const float4*)(g_arp1 + lane * 8);
        float4 a0 = ap[0], a1 = ap[1], b0 = bp[0], b1 = bp[1];
        av[0]=a0.x; av[1]=a0.y; av[2]=a0.z; av[3]=a0.w;
        av[4]=a1.x; av[5]=a1.y; av[6]=a1.z; av[7]=a1.w;
        bv[0]=b0.x; bv[1]=b0.y; bv[2]=b0.z; bv[3]=b0.w;
        bv[4]=b1.x; bv[5]=b1.y; bv[6]=b1.z; bv[7]=b1.w;
    }
    for (int row = wid; row < nr; row += 8) {
        const float4* f4 = (const float4*)(stage + row * STP + lane * 8);
        float4 f0 = f4[0], f1 = f4[1];
        float pa[8] = {f0.x*av[0], f0.y*av[1], f0.z*av[2], f0.w*av[3],
                       f1.x*av[4], f1.y*av[5], f1.z*av[6], f1.w*av[7]};
        float pb[8] = {f0.x*bv[0], f0.y*bv[1], f0.z*bv[2], f0.w*bv[3],
                       f1.x*bv[4], f1.y*bv[5], f1.z*bv[6], f1.w*bv[7]};
#pragma unroll
        for (int h = 0; h < 8; h++) {
#pragma unroll
            for (int off = 16; off; off >>= 1) {
                pa[h] += __shfl_xor_sync(0xffffffffu, pa[h], off);
                pb[h] += __shfl_xor_sync(0xffffffffu, pb[h], off);
            }
        }
        if (lane == 0) {
            float* elp = g_el + (size_t)(r0 + row) * HH;
            float* erp = g_er + (size_t)(r0 + row) * HH;
            *(float4*)(elp)     = make_float4(pa[0], pa[1], pa[2], pa[3]);
            *(float4*)(elp + 4) = make_float4(pa[4], pa[5], pa[6], pa[7]);
            *(float4*)(erp)     = make_float4(pb[0], pb[1], pb[2], pb[3]);
            *(float4*)(erp + 4) = make_float4(pb[4], pb[5], pb[6], pb[7]);
        }
    }
}

// ---------------- fused agg1 + layer-2 GEMM + el/er + fp16 feat ---------------
// Writes layer-2 state to g_feat2/g_el2/g_er2 (layer-1 buffers are read by
// other blocks' aggregation phase concurrently — must not be overwritten).
__global__ __launch_bounds__(256, 2) void fuse2_kernel(const float* __restrict__ b1,
                                                       int n) {
    constexpr int K = DD;       // 32
    constexpr int XP = K + 4;   // 36
    constexpr int WP = 264;
    constexpr int STP = 260;
    extern __shared__ float sh[];
    unsigned* Xsh = (unsigned*)sh;                       // [TRB][XP]
    unsigned* Wsh = (unsigned*)(sh + TRB * XP);          // [K][WP]
    int tid = threadIdx.x;
    int wid = tid >> 5, lane = tid & 31;
    int g = lane >> 2, tg = lane & 3;
    int warpM = wid >> 2, warpN = wid & 3;
    int nbase = warpN * 64;

    int r0 = blockIdx.x * TRB;
    int nr = min(TRB, n - r0);

    // phase A: aggregate layer 1 for my warp's 8 rows -> Xsh (tf32 bits)
    for (int j = 0; j < 8; j++) {
        int local = wid * 8 + j;
        int node = r0 + local;
        float val = 0.f;
        if (local < nr) val = agg_node<true>(node, lane, g_feat, g_el, g_er, b1);
        Xsh[local * XP + lane] = f2tf32(val);
    }

    // phase A2: stage W2
    for (int idx = tid; idx < K * HD; idx += 256) {
        int kk = idx >> 8, j = idx & 255;
        Wsh[kk * WP + j] = ((const unsigned*)g_Wp2)[idx];
    }
    __syncthreads();

    // phase B: MMA
    float acc[2][8][4];
#pragma unroll
    for (int m = 0; m < 2; m++)
#pragma unroll
        for (int t = 0; t < 8; t++)
#pragma unroll
            for (int c = 0; c < 4; c++) acc[m][t][c] = 0.f;

#pragma unroll
    for (int kk = 0; kk < K; kk += 8) {
        unsigned a[2][4];
#pragma unroll
        for (int m = 0; m < 2; m++) {
            int rb = warpM * 32 + m * 16;
            a[m][0] = Xsh[(rb + g) * XP + kk + tg];
            a[m][1] = Xsh[(rb + g + 8) * XP + kk + tg];
            a[m][2] = Xsh[(rb + g) * XP + kk + tg + 4];
            a[m][3] = Xsh[(rb + g + 8) * XP + kk + tg + 4];
        }
#pragma unroll
        for (int t = 0; t < 8; t++) {
            int ncol = nbase + t * 8 + g;
            unsigned b0 = Wsh[(kk + tg) * WP + ncol];
            unsigned b1w = Wsh[(kk + tg + 4) * WP + ncol];
            mma_tf32(acc[0][t][0], acc[0][t][1], acc[0][t][2], acc[0][t][3],
                     a[0][0], a[0][1], a[0][2], a[0][3], b0, b1w);
            mma_tf32(acc[1][t][0], acc[1][t][1], acc[1][t][2], acc[1][t][3],
                     a[1][0], a[1][1], a[1][2], a[1][3], b0, b1w);
        }
    }

    __syncthreads();
    float* stage = sh;          // [TRB][STP]
#pragma unroll
    for (int m = 0; m < 2; m++) {
        int rb = warpM * 32 + m * 16;
#pragma unroll
        for (int t = 0; t < 8; t++) {
            int c = nbase + t * 8 + 2 * tg;
            *(float2*)&stage[(rb + g) * STP + c] =
                make_float2(acc[m][t][0], acc[m][t][1]);
            *(float2*)&stage[(rb + g + 8) * STP + c] =
                make_float2(acc[m][t][2], acc[m][t][3]);
        }
    }
    __syncthreads();

    for (int i = tid; i < nr * 32; i += 256) {
        int row = i >> 5, cg = i & 31;
        const float4* s4 = (const float4*)&stage[row * STP + cg * 8];
        float4 f0 = s4[0], f1 = s4[1];
        __half2 h0 = __floats2half2_rn(f0.x, f0.y);
        __half2 h1 = __floats2half2_rn(f0.z, f0.w);
        __half2 h2 = __floats2half2_rn(f1.x, f1.y);
        __half2 h3 = __floats2half2_rn(f1.z, f1.w);
        uint4 u = make_uint4(*(unsigned*)&h0, *(unsigned*)&h1,
                             *(unsigned*)&h2, *(unsigned*)&h3);
        *(uint4*)(&g_feat2[(size_t)(r0 + row) * HD + cg * 8]) = u;
    }

    float av[8], bv[8];
    {
        const float4* ap = (const float4*)(g_alp2 + lane * 8);
        const float4* bp = (const float4*)(g_arp2 + lane * 8);
        float4 a0 = ap[0], a1 = ap[1], b0 = bp[0], b1w = bp[1];
        av[0]=a0.x; av[1]=a0.y; av[2]=a0.z; av[3]=a0.w;
        av[4]=a1.x; av[5]=a1.y; av[6]=a1.z; av[7]=a1.w;
        bv[0]=b0.x; bv[1]=b0.y; bv[2]=b0.z; bv[3]=b0.w;
        bv[4]=b1w.x; bv[5]=b1w.y; bv[6]=b1w.z; bv[7]=b1w.w;
    }
    for (int row = wid; row < nr; row += 8) {
        const float4* f4 = (const float4*)(stage + row * STP + lane * 8);
        float4 f0 = f4[0], f1 = f4[1];
        float pa[8] = {f0.x*av[0], f0.y*av[1], f0.z*av[2], f0.w*av[3],
                       f1.x*av[4], f1.y*av[5], f1.z*av[6], f1.w*av[7]};
        float pb[8] = {f0.x*bv[0], f0.y*bv[1], f0.z*bv[2], f0.w*bv[3],
                       f1.x*bv[4], f1.y*bv[5], f1.z*bv[6], f1.w*bv[7]};
#pragma unroll
        for (int h = 0; h < 8; h++) {
#pragma unroll
            for (int off = 16; off; off >>= 1) {
                pa[h] += __shfl_xor_sync(0xffffffffu, pa[h], off);
                pb[h] += __shfl_xor_sync(0xffffffffu, pb[h], off);
            }
        }
        if (lane == 0) {
            float* elp = g_el2 + (size_t)(r0 + row) * HH;
            float* erp = g_er2 + (size_t)(r0 + row) * HH;
            *(float4*)(elp)     = make_float4(pa[0], pa[1], pa[2], pa[3]);
            *(float4*)(elp + 4) = make_float4(pa[4], pa[5], pa[6], pa[7]);
            *(float4*)(erp)     = make_float4(pb[0], pb[1], pb[2], pb[3]);
            *(float4*)(erp + 4) = make_float4(pb[4], pb[5], pb[6], pb[7]);
        }
    }
}

// ---------------- final aggregation (layer 2) ----------------------------------
__global__ void agg2_kernel(const float* __restrict__ bias,
                            float* __restrict__ out) {
    int node = blockIdx.x * (blockDim.x >> 5) + (threadIdx.x >> 5);
    if (node >= NN) return;
    int lane = threadIdx.x & 31;
    out[node * DD + lane] = agg_node<false>(node, lane, g_feat2, g_el2, g_er2, bias);
}

// ---------------- stream/event resources (created once, pre-capture) ----------
struct HxRes {
    cudaStream_t s2;
    cudaEvent_t e0, e1;
    HxRes() {
        cudaStreamCreateWithFlags(&s2, cudaStreamNonBlocking);
        cudaEventCreateWithFlags(&e0, cudaEventDisableTiming);
        cudaEventCreateWithFlags(&e1, cudaEventDisableTiming);
    }
};
static HxRes& hx() { static HxRes r; return r; }

// ---------------- launcher -----------------------------------------------------
extern "C" void kernel_launch(void* const* d_in, const int* in_sizes, int n_in,
                              void* d_out, int out_size) {
    const float* x   = (const float*)d_in[0];
    const int*   src = (const int*)d_in[1];
    const int*   dst = (const int*)d_in[2];
    const float* W1  = (const float*)d_in[3];
    const float* al1 = (const float*)d_in[4];
    const float* ar1 = (const float*)d_in[5];
    const float* b1  = (const float*)d_in[6];
    const float* W2  = (const float*)d_in[7];
    const float* al2 = (const float*)d_in[8];
    const float* ar2 = (const float*)d_in[9];
    const float* b2  = (const float*)d_in[10];
    float* out = (float*)d_out;

    const int NTB = (NN + TRB - 1) / TRB;  // 313 tiles
    constexpr int smem1 = (64 * 264 + 64 * 132) * sizeof(float);   // 101376
    constexpr int smemF = (64 * 260) * sizeof(float);              // 66560 (stage max)
    cudaFuncSetAttribute(gemm1_kernel,
                         cudaFuncAttributeMaxDynamicSharedMemorySize, smem1);
    cudaFuncSetAttribute(fuse2_kernel,
                         cudaFuncAttributeMaxDynamicSharedMemorySize, smemF);

    HxRes& R = hx();

    // fork: CSR chain on s2, overlapped with perm + gemm1
    cudaEventRecord(R.e0, 0);
    cudaStreamWaitEvent(R.s2, R.e0, 0);
    hist_kernel<<<(EE + 255) / 256, 256, 0, R.s2>>>(dst);
    scan_kernel<<<1, 1024, 0, R.s2>>>();
    scatter_kernel<<<(EE + 255) / 256, 256, 0, R.s2>>>(src, dst);
    cudaEventRecord(R.e1, R.s2);

    // main stream: layer-1 GEMM (+fused el/er, fp16 feat)
    perm_kernel<<<(F1 * HD + 255) / 256, 256>>>(W1, al1, ar1, W2, al2, ar2);
    gemm1_kernel<<<NTB, 256, smem1>>>(x, NN);

    // join; fused agg1+gemm2, then final aggregation
    cudaStreamWaitEvent(0, R.e1, 0);
    fuse2_kernel<<<NTB, 256, smemF>>>(b1, NN);
    agg2_kernel<<<(NN + 7) / 8, 256>>>(b2, out);
}

// round 9
// speedup vs baseline: 1.1275x; 1.1275x over previous
#include <cuda_runtime.h>
#include <cuda_fp16.h>
#include <cuda_bf16.h>

#define NN 20000
#define EE 320000
#define HH 8
#define DD 32
#define F1 128
#define HD 256   // H*D
#define TRB 64   // gemm row tile

// ---------------- scratch (device globals; no allocation allowed) -------------
__device__ __half g_feat[NN * HD];     // [N, dim*8+head] fp16 features
__device__ float g_el[NN * HH];
__device__ float g_er[NN * HH];
__device__ float g_h[NN * DD];         // layer-1 output (fp32)
__device__ int   g_cnt[NN];            // INVARIANT: zero on entry to every call
__device__ int   g_rowptr[NN + 1];
__device__ int   g_fill[NN];
__device__ int   g_esrc[EE];

__device__ __forceinline__ unsigned f2tf32(float f) {
    unsigned u;
    asm("cvt.rna.tf32.f32 %0, %1;" : "=r"(u) : "f"(f));
    return u;
}

__device__ __forceinline__ void mma_tf32(float& d0, float& d1, float& d2, float& d3,
                                         unsigned a0, unsigned a1, unsigned a2, unsigned a3,
                                         unsigned b0, unsigned b1) {
    asm volatile("mma.sync.aligned.m16n8k8.row.col.f32.tf32.tf32.f32 "
                 "{%0,%1,%2,%3}, {%4,%5,%6,%7}, {%8,%9}, {%0,%1,%2,%3};"
                 : "+f"(d0), "+f"(d1), "+f"(d2), "+f"(d3)
                 : "r"(a0), "r"(a1), "r"(a2), "r"(a3), "r"(b0), "r"(b1));
}

// ---------------- CSR chain (runs on forked stream) ---------------------------
__global__ void hist_kernel(const int* __restrict__ dst) {
    int e = blockIdx.x * blockDim.x + threadIdx.x;
    if (e < EE) atomicAdd(&g_cnt[dst[e]], 1);
}

__global__ void scan_kernel() {   // also restores g_cnt = 0 invariant
    __shared__ int ssum[1024];
    int t = threadIdx.x;
    const int chunk = (NN + 1023) / 1024;
    int b = t * chunk, e = min(b + chunk, NN);
    int s = 0;
    for (int i = b; i < e; i++) s += g_cnt[i];
    ssum[t] = s;
    __syncthreads();
    for (int off = 1; off < 1024; off <<= 1) {
        int v = (t >= off) ? ssum[t - off] : 0;
        __syncthreads();
        ssum[t] += v;
        __syncthreads();
    }
    int pref = (t > 0) ? ssum[t - 1] : 0;
    for (int i = b; i < e; i++) {
        int c = g_cnt[i];
        g_rowptr[i] = pref;
        g_fill[i]   = pref;
        g_cnt[i]    = 0;
        pref += c;
    }
    if (t == 1023) g_rowptr[NN] = ssum[1023];
}

__global__ void scatter_kernel(const int* __restrict__ src,
                               const int* __restrict__ dst) {
    int e = blockIdx.x * blockDim.x + threadIdx.x;
    if (e < EE) {
        int p = atomicAdd(&g_fill[dst[e]], 1);
        g_esrc[p] = src[e];
    }
}

// ---------------- tensor-core GEMM + fused el/er + fp16 feat ------------------
// 256 threads = 8 warps (2 Mgroups x 4 Ngroups). Tile 64 rows x 256 cols.
// W loaded directly from the input tensor with the head/dim column permutation
// L(j) = ((j&7)<<5)|(j>>3) applied inline (no separate perm kernel needed).
template <int K>
__global__ __launch_bounds__(256, 2) void gemm_tc_kernel(const float* __restrict__ X,
                                                         const float* __restrict__ W,
                                                         const float* __restrict__ al,
                                                         const float* __restrict__ ar,
                                                         int n) {
    constexpr int KC = (K > 64) ? 64 : K;   // W chunk rows
    constexpr int XP = K + 4;               // X row pad
    constexpr int WP = 264;                 // W row pad
    constexpr int STP = 260;                // stage row pad
    extern __shared__ float sh[];
    unsigned* Wsh = (unsigned*)sh;                  // [KC][WP]
    unsigned* Xsh = (unsigned*)(sh + KC * WP);      // [TRB][XP]
    int tid = threadIdx.x;
    int wid = tid >> 5, lane = tid & 31;
    int g = lane >> 2, tg = lane & 3;
    int warpM = wid >> 2, warpN = wid & 3;
    int nbase = warpN * 64;

    int r0 = blockIdx.x * TRB;
    int nr = min(TRB, n - r0);

    // X tile -> smem as tf32 bits (zero pad tail rows)
    for (int idx = tid; idx < TRB * K; idx += 256) {
        int r = idx / K, c = idx % K;
        float v = (r < nr) ? X[(size_t)(r0 + r) * K + c] : 0.f;
        Xsh[r * XP + c] = f2tf32(v);
    }

    float acc[2][8][4];
#pragma unroll
    for (int m = 0; m < 2; m++)
#pragma unroll
        for (int t = 0; t < 8; t++)
#pragma unroll
            for (int c = 0; c < 4; c++) acc[m][t][c] = 0.f;

    for (int kc = 0; kc < K; kc += KC) {
        __syncthreads();
        for (int idx = tid; idx < KC * HD; idx += 256) {
            int kk = idx >> 8, j = idx & 255;
            int L = ((j & 7) << 5) | (j >> 3);
            Wsh[kk * WP + j] = f2tf32(W[(size_t)(kc + kk) * HD + L]);
        }
        __syncthreads();

#pragma unroll
        for (int kk = 0; kk < KC; kk += 8) {
            int k0 = kc + kk;
            unsigned a[2][4];
#pragma unroll
            for (int m = 0; m < 2; m++) {
                int rb = warpM * 32 + m * 16;
                a[m][0] = Xsh[(rb + g) * XP + k0 + tg];
                a[m][1] = Xsh[(rb + g + 8) * XP + k0 + tg];
                a[m][2] = Xsh[(rb + g) * XP + k0 + tg + 4];
                a[m][3] = Xsh[(rb + g + 8) * XP + k0 + tg + 4];
            }
#pragma unroll
            for (int t = 0; t < 8; t++) {
                int ncol = nbase + t * 8 + g;
                unsigned b0 = Wsh[(kk + tg) * WP + ncol];
                unsigned b1 = Wsh[(kk + tg + 4) * WP + ncol];
                mma_tf32(acc[0][t][0], acc[0][t][1], acc[0][t][2], acc[0][t][3],
                         a[0][0], a[0][1], a[0][2], a[0][3], b0, b1);
                mma_tf32(acc[1][t][0], acc[1][t][1], acc[1][t][2], acc[1][t][3],
                         a[1][0], a[1][1], a[1][2], a[1][3], b0, b1);
            }
        }
    }

    // stage fp32 result to smem (reuse W/X space)
    __syncthreads();
    float* stage = sh;          // [TRB][STP]
#pragma unroll
    for (int m = 0; m < 2; m++) {
        int rb = warpM * 32 + m * 16;
#pragma unroll
        for (int t = 0; t < 8; t++) {
            int c = nbase + t * 8 + 2 * tg;
            *(float2*)&stage[(rb + g) * STP + c] =
                make_float2(acc[m][t][0], acc[m][t][1]);
            *(float2*)&stage[(rb + g + 8) * STP + c] =
                make_float2(acc[m][t][2], acc[m][t][3]);
        }
    }
    __syncthreads();

    // fp16 feat writeout (coalesced)
    for (int i = tid; i < nr * 32; i += 256) {
        int row = i >> 5, cg = i & 31;
        const float4* s4 = (const float4*)&stage[row * STP + cg * 8];
        float4 f0 = s4[0], f1 = s4[1];
        __half2 h0 = __floats2half2_rn(f0.x, f0.y);
        __half2 h1 = __floats2half2_rn(f0.z, f0.w);
        __half2 h2 = __floats2half2_rn(f1.x, f1.y);
        __half2 h3 = __floats2half2_rn(f1.z, f1.w);
        uint4 u = make_uint4(*(unsigned*)&h0, *(unsigned*)&h1,
                             *(unsigned*)&h2, *(unsigned*)&h3);
        *(uint4*)(&g_feat[(size_t)(r0 + row) * HD + cg * 8]) = u;
    }

    // el/er: warp per row. Permuted attention vec element (lane*8+q) maps to
    // al[q*32+lane] (algebraic collapse of L) — coalesced direct load.
    float av[8], bv[8];
#pragma unroll
    for (int q = 0; q < 8; q++) {
        av[q] = al[q * DD + lane];
        bv[q] = ar[q * DD + lane];
    }
    for (int row = wid; row < nr; row += 8) {
        const float4* f4 = (const float4*)(stage + row * STP + lane * 8);
        float4 f0 = f4[0], f1 = f4[1];
        float pa[8] = {f0.x*av[0], f0.y*av[1], f0.z*av[2], f0.w*av[3],
                       f1.x*av[4], f1.y*av[5], f1.z*av[6], f1.w*av[7]};
        float pb[8] = {f0.x*bv[0], f0.y*bv[1], f0.z*bv[2], f0.w*bv[3],
                       f1.x*bv[4], f1.y*bv[5], f1.z*bv[6], f1.w*bv[7]};
#pragma unroll
        for (int h = 0; h < 8; h++) {
#pragma unroll
            for (int off = 16; off; off >>= 1) {
                pa[h] += __shfl_xor_sync(0xffffffffu, pa[h], off);
                pb[h] += __shfl_xor_sync(0xffffffffu, pb[h], off);
            }
        }
        if (lane == 0) {
            float* elp = g_el + (size_t)(r0 + row) * HH;
            float* erp = g_er + (size_t)(r0 + row) * HH;
            *(float4*)(elp)     = make_float4(pa[0], pa[1], pa[2], pa[3]);
            *(float4*)(elp + 4) = make_float4(pa[4], pa[5], pa[6], pa[7]);
            *(float4*)(erp)     = make_float4(pb[0], pb[1], pb[2], pb[3]);
            *(float4*)(erp + 4) = make_float4(pb[4], pb[5], pb[6], pb[7]);
        }
    }
}

// ---------------- aggregation (warp per dst node, unroll x4, fp16 feat) -------
template <bool RELU_BEFORE_MEAN>
__global__ void agg_kernel(const float* __restrict__ bias,
                           float* __restrict__ out) {
    int node = blockIdx.x * (blockDim.x >> 5) + (threadIdx.x >> 5);
    if (node >= NN) return;
    int lane = threadIdx.x & 31;
    int hh = lane & 7;
    float er_l = g_er[node * HH + hh];
    int beg = g_rowptr[node], end = g_rowptr[node + 1];

    float acc[8];
#pragma unroll
    for (int h = 0; h < 8; h++) acc[h] = 0.f;
    float den_l = 0.f;

    int i = beg;
    for (; i + 4 <= end; i += 4) {
        int s0 = g_esrc[i + 0], s1 = g_esrc[i + 1];
        int s2 = g_esrc[i + 2], s3 = g_esrc[i + 3];
        float el0 = __ldg(g_el + s0 * HH + hh);
        float el1 = __ldg(g_el + s1 * HH + hh);
        float el2 = __ldg(g_el + s2 * HH + hh);
        float el3 = __ldg(g_el + s3 * HH + hh);
        uint4 u0 = *(const uint4*)(&g_feat[(size_t)s0 * HD + lane * 8]);
        uint4 u1 = *(const uint4*)(&g_feat[(size_t)s1 * HD + lane * 8]);
        uint4 u2 = *(const uint4*)(&g_feat[(size_t)s2 * HD + lane * 8]);
        uint4 u3 = *(const uint4*)(&g_feat[(size_t)s3 * HD + lane * 8]);
        float v0 = el0 + er_l; v0 = v0 > 0.f ? v0 : 0.2f * v0;
        float v1 = el1 + er_l; v1 = v1 > 0.f ? v1 : 0.2f * v1;
        float v2 = el2 + er_l; v2 = v2 > 0.f ? v2 : 0.2f * v2;
        float v3 = el3 + er_l; v3 = v3 > 0.f ? v3 : 0.2f * v3;
        float e0 = __expf(v0), e1 = __expf(v1);
        float e2 = __expf(v2), e3 = __expf(v3);
        den_l += (e0 + e1) + (e2 + e3);
        const unsigned* p0 = &u0.x;
        const unsigned* p1 = &u1.x;
        const unsigned* p2 = &u2.x;
        const unsigned* p3 = &u3.x;
#pragma unroll
        for (int q = 0; q < 4; q++) {       // q = head pair (2q, 2q+1)
            float2 f0 = __half22float2(*(const __half2*)&p0[q]);
            float2 f1 = __half22float2(*(const __half2*)&p1[q]);
            float2 f2 = __half22float2(*(const __half2*)&p2[q]);
            float2 f3 = __half22float2(*(const __half2*)&p3[q]);
            float wa0 = __shfl_sync(0xffffffffu, e0, 2 * q);
            float wa1 = __shfl_sync(0xffffffffu, e0, 2 * q + 1);
            float wb0 = __shfl_sync(0xffffffffu, e1, 2 * q);
            float wb1 = __shfl_sync(0xffffffffu, e1, 2 * q + 1);
            float wc0 = __shfl_sync(0xffffffffu, e2, 2 * q);
            float wc1 = __shfl_sync(0xffffffffu, e2, 2 * q + 1);
            float wd0 = __shfl_sync(0xffffffffu, e3, 2 * q);
            float wd1 = __shfl_sync(0xffffffffu, e3, 2 * q + 1);
            acc[2 * q]     = fmaf(wa0, f0.x, acc[2 * q]);
            acc[2 * q + 1] = fmaf(wa1, f0.y, acc[2 * q + 1]);
            acc[2 * q]     = fmaf(wb0, f1.x, acc[2 * q]);
            acc[2 * q + 1] = fmaf(wb1, f1.y, acc[2 * q + 1]);
            acc[2 * q]     = fmaf(wc0, f2.x, acc[2 * q]);
            acc[2 * q + 1] = fmaf(wc1, f2.y, acc[2 * q + 1]);
            acc[2 * q]     = fmaf(wd0, f3.x, acc[2 * q]);
            acc[2 * q + 1] = fmaf(wd1, f3.y, acc[2 * q + 1]);
        }
    }
    for (; i < end; i++) {
        int s = g_esrc[i];
        float elv = __ldg(g_el + s * HH + hh);
        uint4 u0 = *(const uint4*)(&g_feat[(size_t)s * HD + lane * 8]);
        float v = elv + er_l; v = v > 0.f ? v : 0.2f * v;
        float e = __expf(v);
        den_l += e;
        const unsigned* p0 = &u0.x;
#pragma unroll
        for (int q = 0; q < 4; q++) {
            float2 f0 = __half22float2(*(const __half2*)&p0[q]);
            float w0 = __shfl_sync(0xffffffffu, e, 2 * q);
            float w1 = __shfl_sync(0xffffffffu, e, 2 * q + 1);
            acc[2 * q]     = fmaf(w0, f0.x, acc[2 * q]);
            acc[2 * q + 1] = fmaf(w1, f0.y, acc[2 * q + 1]);
        }
    }

    float sum = 0.f;
#pragma unroll
    for (int h = 0; h < 8; h++) {
        float dh = __shfl_sync(0xffffffffu, den_l, h);
        float r = (dh > 0.f) ? __fdividef(acc[h], dh) : 0.f;
        r += bias[h * DD + lane];
        if (RELU_BEFORE_MEAN) r = fmaxf(r, 0.f);
        sum += r;
    }
    out[node * DD + lane] = sum * 0.125f;
}

// ---------------- stream/event resources (created once, pre-capture) ----------
struct HxRes {
    cudaStream_t s2;
    cudaEvent_t e0, e1;
    HxRes() {
        cudaStreamCreateWithFlags(&s2, cudaStreamNonBlocking);
        cudaEventCreateWithFlags(&e0, cudaEventDisableTiming);
        cudaEventCreateWithFlags(&e1, cudaEventDisableTiming);
    }
};
static HxRes& hx() { static HxRes r; return r; }

// ---------------- launcher -----------------------------------------------------
extern "C" void kernel_launch(void* const* d_in, const int* in_sizes, int n_in,
                              void* d_out, int out_size) {
    const float* x   = (const float*)d_in[0];
    const int*   src = (const int*)d_in[1];
    const int*   dst = (const int*)d_in[2];
    const float* W1  = (const float*)d_in[3];
    const float* al1 = (const float*)d_in[4];
    const float* ar1 = (const float*)d_in[5];
    const float* b1  = (const float*)d_in[6];
    const float* W2  = (const float*)d_in[7];
    const float* al2 = (const float*)d_in[8];
    const float* ar2 = (const float*)d_in[9];
    const float* b2  = (const float*)d_in[10];
    float* out = (float*)d_out;

    float* hbuf;
    cudaGetSymbolAddress((void**)&hbuf, g_h);

    const int NTB = (NN + TRB - 1) / TRB;  // 313 tiles
    constexpr int smem1 = (64 * 264 + 64 * 132) * sizeof(float);   // 101376
    constexpr int smem2 = (64 * 260) * sizeof(float);              // 66560
    cudaFuncSetAttribute(gemm_tc_kernel<F1>,
                         cudaFuncAttributeMaxDynamicSharedMemorySize, smem1);
    cudaFuncSetAttribute(gemm_tc_kernel<DD>,
                         cudaFuncAttributeMaxDynamicSharedMemorySize, smem2);

    HxRes& R = hx();

    // fork: CSR chain on s2, overlapped with gemm1
    cudaEventRecord(R.e0, 0);
    cudaStreamWaitEvent(R.s2, R.e0, 0);
    hist_kernel<<<(EE + 255) / 256, 256, 0, R.s2>>>(dst);
    scan_kernel<<<1, 1024, 0, R.s2>>>();
    scatter_kernel<<<(EE + 255) / 256, 256, 0, R.s2>>>(src, dst);
    cudaEventRecord(R.e1, R.s2);

    // main stream: layer-1 GEMM (+fused el/er, fp16 feat) — no perm prologue
    gemm_tc_kernel<F1><<<NTB, 256, smem1>>>(x, W1, al1, ar1, NN);

    // join, then aggregate layer 1
    cudaStreamWaitEvent(0, R.e1, 0);
    agg_kernel<true><<<(NN + 7) / 8, 256>>>(b1, hbuf);

    // layer 2
    gemm_tc_kernel<DD><<<NTB, 256, smem2>>>(hbuf, W2, al2, ar2, NN);
    agg_kernel<false><<<(NN + 7) / 8, 256>>>(b2, out);
}

// round 10
// speedup vs baseline: 1.4093x; 1.2499x over previous
#include <cuda_runtime.h>
#include <cuda_fp16.h>
#include <cuda_bf16.h>

#define NN 20000
#define EE 320000
#define HH 8
#define DD 32
#define F1 128
#define HD 256   // H*D
#define TRB 64   // gemm row tile

// ---------------- scratch (device globals; no allocation allowed) -------------
__device__ __half g_feat[NN * HD];     // [N, dim*8+head] fp16 features
__device__ float g_el[NN * HH];
__device__ float g_er[NN * HH];
__device__ float g_h[NN * DD];         // layer-1 output (fp32)
__device__ float g_Wp1[F1 * HD];       // tf32 bits, permuted cols
__device__ float g_Wp2[DD * HD];
__device__ float g_alp1[HD], g_arp1[HD];
__device__ float g_alp2[HD], g_arp2[HD];
__device__ int   g_cnt[NN];            // INVARIANT: zero on entry to every call
__device__ int   g_rowptr[NN + 1];
__device__ int   g_fill[NN];
__device__ int   g_esrc[EE];

__device__ __forceinline__ unsigned f2tf32(float f) {
    unsigned u;
    asm("cvt.rna.tf32.f32 %0, %1;" : "=r"(u) : "f"(f));
    return u;
}

__device__ __forceinline__ void mma_tf32(float& d0, float& d1, float& d2, float& d3,
                                         unsigned a0, unsigned a1, unsigned a2, unsigned a3,
                                         unsigned b0, unsigned b1) {
    asm volatile("mma.sync.aligned.m16n8k8.row.col.f32.tf32.tf32.f32 "
                 "{%0,%1,%2,%3}, {%4,%5,%6,%7}, {%8,%9}, {%0,%1,%2,%3};"
                 : "+f"(d0), "+f"(d1), "+f"(d2), "+f"(d3)
                 : "r"(a0), "r"(a1), "r"(a2), "r"(a3), "r"(b0), "r"(b1));
}

// ---------------- weight permutation + tf32 conversion ------------------------
__global__ void perm_kernel(const float* __restrict__ W1,
                            const float* __restrict__ al1,
                            const float* __restrict__ ar1,
                            const float* __restrict__ W2,
                            const float* __restrict__ al2,
                            const float* __restrict__ ar2) {
    int t = blockIdx.x * 256 + threadIdx.x;
    if (t < F1 * HD) {
        int k = t >> 8, j = t & 255;
        int L = ((j & 7) << 5) | (j >> 3);
        g_Wp1[t] = __uint_as_float(f2tf32(W1[k * HD + L]));
    }
    if (t < DD * HD) {
        int k = t >> 8, j = t & 255;
        int L = ((j & 7) << 5) | (j >> 3);
        g_Wp2[t] = __uint_as_float(f2tf32(W2[k * HD + L]));
    }
    if (t < HD) {
        int L = ((t & 7) << 5) | (t >> 3);
        g_alp1[t] = al1[L]; g_arp1[t] = ar1[L];
        g_alp2[t] = al2[L]; g_arp2[t] = ar2[L];
    }
}

// ---------------- CSR chain (runs on forked stream) ---------------------------
__global__ void hist_kernel(const int* __restrict__ dst) {
    int e = blockIdx.x * blockDim.x + threadIdx.x;
    if (e < EE) atomicAdd(&g_cnt[dst[e]], 1);
}

__global__ void scan_kernel() {   // also restores g_cnt = 0 invariant
    __shared__ int ssum[1024];
    int t = threadIdx.x;
    const int chunk = (NN + 1023) / 1024;
    int b = t * chunk, e = min(b + chunk, NN);
    int s = 0;
    for (int i = b; i < e; i++) s += g_cnt[i];
    ssum[t] = s;
    __syncthreads();
    for (int off = 1; off < 1024; off <<= 1) {
        int v = (t >= off) ? ssum[t - off] : 0;
        __syncthreads();
        ssum[t] += v;
        __syncthreads();
    }
    int pref = (t > 0) ? ssum[t - 1] : 0;
    for (int i = b; i < e; i++) {
        int c = g_cnt[i];
        g_rowptr[i] = pref;
        g_fill[i]   = pref;
        g_cnt[i]    = 0;
        pref += c;
    }
    if (t == 1023) g_rowptr[NN] = ssum[1023];
}

__global__ void scatter_kernel(const int* __restrict__ src,
                               const int* __restrict__ dst) {
    int e = blockIdx.x * blockDim.x + threadIdx.x;
    if (e < EE) {
        int p = atomicAdd(&g_fill[dst[e]], 1);
        g_esrc[p] = src[e];
    }
}

// ---------------- tensor-core GEMM + fused el/er + fp16 feat ------------------
// 256 threads = 8 warps (2 Mgroups x 4 Ngroups). Tile 64 rows x 256 cols.
template <int K>
__global__ __launch_bounds__(256, 2) void gemm_tc_kernel(const float* __restrict__ X,
                                                         const float* __restrict__ Wp,
                                                         const float* __restrict__ alp,
                                                         const float* __restrict__ arp,
                                                         int n) {
    constexpr int KC = (K > 64) ? 64 : K;   // W chunk rows
    constexpr int XP = K + 4;               // X row pad
    constexpr int WP = 264;                 // W row pad
    constexpr int STP = 260;                // stage row pad
    extern __shared__ float sh[];
    unsigned* Wsh = (unsigned*)sh;                  // [KC][WP]
    unsigned* Xsh = (unsigned*)(sh + KC * WP);      // [TRB][XP]
    int tid = threadIdx.x;
    int wid = tid >> 5, lane = tid & 31;
    int g = lane >> 2, tg = lane & 3;
    int warpM = wid >> 2, warpN = wid & 3;
    int nbase = warpN * 64;

    int r0 = blockIdx.x * TRB;
    int nr = min(TRB, n - r0);

    // X tile -> smem as tf32 bits (zero pad tail rows)
    for (int idx = tid; idx < TRB * K; idx += 256) {
        int r = idx / K, c = idx % K;
        float v = (r < nr) ? X[(size_t)(r0 + r) * K + c] : 0.f;
        Xsh[r * XP + c] = f2tf32(v);
    }

    float acc[2][8][4];
#pragma unroll
    for (int m = 0; m < 2; m++)
#pragma unroll
        for (int t = 0; t < 8; t++)
#pragma unroll
            for (int c = 0; c < 4; c++) acc[m][t][c] = 0.f;

    const unsigned* WpU = (const unsigned*)Wp;
    for (int kc = 0; kc < K; kc += KC) {
        __syncthreads();
        for (int idx = tid; idx < KC * HD; idx += 256) {
            int kk = idx >> 8, j = idx & 255;
            Wsh[kk * WP + j] = WpU[(kc + kk) * HD + j];
        }
        __syncthreads();

#pragma unroll
        for (int kk = 0; kk < KC; kk += 8) {
            int k0 = kc + kk;
            unsigned a[2][4];
#pragma unroll
            for (int m = 0; m < 2; m++) {
                int rb = warpM * 32 + m * 16;
                a[m][0] = Xsh[(rb + g) * XP + k0 + tg];
                a[m][1] = Xsh[(rb + g + 8) * XP + k0 + tg];
                a[m][2] = Xsh[(rb + g) * XP + k0 + tg + 4];
                a[m][3] = Xsh[(rb + g + 8) * XP + k0 + tg + 4];
            }
#pragma unroll
            for (int t = 0; t < 8; t++) {
                int ncol = nbase + t * 8 + g;
                unsigned b0 = Wsh[(kk + tg) * WP + ncol];
                unsigned b1 = Wsh[(kk + tg + 4) * WP + ncol];
                mma_tf32(acc[0][t][0], acc[0][t][1], acc[0][t][2], acc[0][t][3],
                         a[0][0], a[0][1], a[0][2], a[0][3], b0, b1);
                mma_tf32(acc[1][t][0], acc[1][t][1], acc[1][t][2], acc[1][t][3],
                         a[1][0], a[1][1], a[1][2], a[1][3], b0, b1);
            }
        }
    }

    // stage fp32 result to smem (reuse W/X space)
    __syncthreads();
    float* stage = sh;          // [TRB][STP]
#pragma unroll
    for (int m = 0; m < 2; m++) {
        int rb = warpM * 32 + m * 16;
#pragma unroll
        for (int t = 0; t < 8; t++) {
            int c = nbase + t * 8 + 2 * tg;
            *(float2*)&stage[(rb + g) * STP + c] =
                make_float2(acc[m][t][0], acc[m][t][1]);
            *(float2*)&stage[(rb + g + 8) * STP + c] =
                make_float2(acc[m][t][2], acc[m][t][3]);
        }
    }
    __syncthreads();

    // fp16 feat writeout (coalesced)
    for (int i = tid; i < nr * 32; i += 256) {
        int row = i >> 5, cg = i & 31;
        const float4* s4 = (const float4*)&stage[row * STP + cg * 8];
        float4 f0 = s4[0], f1 = s4[1];
        __half2 h0 = __floats2half2_rn(f0.x, f0.y);
        __half2 h1 = __floats2half2_rn(f0.z, f0.w);
        __half2 h2 = __floats2half2_rn(f1.x, f1.y);
        __half2 h3 = __floats2half2_rn(f1.z, f1.w);
        uint4 u = make_uint4(*(unsigned*)&h0, *(unsigned*)&h1,
                             *(unsigned*)&h2, *(unsigned*)&h3);
        *(uint4*)(&g_feat[(size_t)(r0 + row) * HD + cg * 8]) = u;
    }

    // el/er: warp per row
    float av[8], bv[8];
    {
        const float4* ap = (const float4*)(alp + lane * 8);
        const float4* bp = (const float4*)(arp + lane * 8);
        float4 a0 = ap[0], a1 = ap[1], b0 = bp[0], b1 = bp[1];
        av[0]=a0.x; av[1]=a0.y; av[2]=a0.z; av[3]=a0.w;
        av[4]=a1.x; av[5]=a1.y; av[6]=a1.z; av[7]=a1.w;
        bv[0]=b0.x; bv[1]=b0.y; bv[2]=b0.z; bv[3]=b0.w;
        bv[4]=b1.x; bv[5]=b1.y; bv[6]=b1.z; bv[7]=b1.w;
    }
    for (int row = wid; row < nr; row += 8) {
        const float4* f4 = (const float4*)(stage + row * STP + lane * 8);
        float4 f0 = f4[0], f1 = f4[1];
        float pa[8] = {f0.x*av[0], f0.y*av[1], f0.z*av[2], f0.w*av[3],
                       f1.x*av[4], f1.y*av[5], f1.z*av[6], f1.w*av[7]};
        float pb[8] = {f0.x*bv[0], f0.y*bv[1], f0.z*bv[2], f0.w*bv[3],
                       f1.x*bv[4], f1.y*bv[5], f1.z*bv[6], f1.w*bv[7]};
#pragma unroll
        for (int h = 0; h < 8; h++) {
#pragma unroll
            for (int off = 16; off; off >>= 1) {
                pa[h] += __shfl_xor_sync(0xffffffffu, pa[h], off);
                pb[h] += __shfl_xor_sync(0xffffffffu, pb[h], off);
            }
        }
        if (lane == 0) {
            float* elp = g_el + (size_t)(r0 + row) * HH;
            float* erp = g_er + (size_t)(r0 + row) * HH;
            *(float4*)(elp)     = make_float4(pa[0], pa[1], pa[2], pa[3]);
            *(float4*)(elp + 4) = make_float4(pa[4], pa[5], pa[6], pa[7]);
            *(float4*)(erp)     = make_float4(pb[0], pb[1], pb[2], pb[3]);
            *(float4*)(erp + 4) = make_float4(pb[4], pb[5], pb[6], pb[7]);
        }
    }
}

// ---------------- aggregation (warp per dst node, unroll x4, fp16 feat) -------
template <bool RELU_BEFORE_MEAN>
__global__ void agg_kernel(const float* __restrict__ bias,
                           float* __restrict__ out) {
    int node = blockIdx.x * (blockDim.x >> 5) + (threadIdx.x >> 5);
    if (node >= NN) return;
    int lane = threadIdx.x & 31;
    int hh = lane & 7;
    float er_l = g_er[node * HH + hh];
    int beg = g_rowptr[node], end = g_rowptr[node + 1];

    float acc[8];
#pragma unroll
    for (int h = 0; h < 8; h++) acc[h] = 0.f;
    float den_l = 0.f;

    int i = beg;
    for (; i + 4 <= end; i += 4) {
        int s0 = g_esrc[i + 0], s1 = g_esrc[i + 1];
        int s2 = g_esrc[i + 2], s3 = g_esrc[i + 3];
        float el0 = __ldg(g_el + s0 * HH + hh);
        float el1 = __ldg(g_el + s1 * HH + hh);
        float el2 = __ldg(g_el + s2 * HH + hh);
        float el3 = __ldg(g_el + s3 * HH + hh);
        uint4 u0 = *(const uint4*)(&g_feat[(size_t)s0 * HD + lane * 8]);
        uint4 u1 = *(const uint4*)(&g_feat[(size_t)s1 * HD + lane * 8]);
        uint4 u2 = *(const uint4*)(&g_feat[(size_t)s2 * HD + lane * 8]);
        uint4 u3 = *(const uint4*)(&g_feat[(size_t)s3 * HD + lane * 8]);
        float v0 = el0 + er_l; v0 = v0 > 0.f ? v0 : 0.2f * v0;
        float v1 = el1 + er_l; v1 = v1 > 0.f ? v1 : 0.2f * v1;
        float v2 = el2 + er_l; v2 = v2 > 0.f ? v2 : 0.2f * v2;
        float v3 = el3 + er_l; v3 = v3 > 0.f ? v3 : 0.2f * v3;
        float e0 = __expf(v0), e1 = __expf(v1);
        float e2 = __expf(v2), e3 = __expf(v3);
        den_l += (e0 + e1) + (e2 + e3);
        const unsigned* p0 = &u0.x;
        const unsigned* p1 = &u1.x;
        const unsigned* p2 = &u2.x;
        const unsigned* p3 = &u3.x;
#pragma unroll
        for (int q = 0; q < 4; q++) {       // q = head pair (2q, 2q+1)
            float2 f0 = __half22float2(*(const __half2*)&p0[q]);
            float2 f1 = __half22float2(*(const __half2*)&p1[q]);
            float2 f2 = __half22float2(*(const __half2*)&p2[q]);
            float2 f3 = __half22float2(*(const __half2*)&p3[q]);
            float wa0 = __shfl_sync(0xffffffffu, e0, 2 * q);
            float wa1 = __shfl_sync(0xffffffffu, e0, 2 * q + 1);
            float wb0 = __shfl_sync(0xffffffffu, e1, 2 * q);
            float wb1 = __shfl_sync(0xffffffffu, e1, 2 * q + 1);
            float wc0 = __shfl_sync(0xffffffffu, e2, 2 * q);
            float wc1 = __shfl_sync(0xffffffffu, e2, 2 * q + 1);
            float wd0 = __shfl_sync(0xffffffffu, e3, 2 * q);
            float wd1 = __shfl_sync(0xffffffffu, e3, 2 * q + 1);
            acc[2 * q]     = fmaf(wa0, f0.x, acc[2 * q]);
            acc[2 * q + 1] = fmaf(wa1, f0.y, acc[2 * q + 1]);
            acc[2 * q]     = fmaf(wb0, f1.x, acc[2 * q]);
            acc[2 * q + 1] = fmaf(wb1, f1.y, acc[2 * q + 1]);
            acc[2 * q]     = fmaf(wc0, f2.x, acc[2 * q]);
            acc[2 * q + 1] = fmaf(wc1, f2.y, acc[2 * q + 1]);
            acc[2 * q]     = fmaf(wd0, f3.x, acc[2 * q]);
            acc[2 * q + 1] = fmaf(wd1, f3.y, acc[2 * q + 1]);
        }
    }
    for (; i < end; i++) {
        int s = g_esrc[i];
        float elv = __ldg(g_el + s * HH + hh);
        uint4 u0 = *(const uint4*)(&g_feat[(size_t)s * HD + lane * 8]);
        float v = elv + er_l; v = v > 0.f ? v : 0.2f * v;
        float e = __expf(v);
        den_l += e;
        const unsigned* p0 = &u0.x;
#pragma unroll
        for (int q = 0; q < 4; q++) {
            float2 f0 = __half22float2(*(const __half2*)&p0[q]);
            float w0 = __shfl_sync(0xffffffffu, e, 2 * q);
            float w1 = __shfl_sync(0xffffffffu, e, 2 * q + 1);
            acc[2 * q]     = fmaf(w0, f0.x, acc[2 * q]);
            acc[2 * q + 1] = fmaf(w1, f0.y, acc[2 * q + 1]);
        }
    }

    float sum = 0.f;
#pragma unroll
    for (int h = 0; h < 8; h++) {
        float dh = __shfl_sync(0xffffffffu, den_l, h);
        float r = (dh > 0.f) ? __fdividef(acc[h], dh) : 0.f;
        r += bias[h * DD + lane];
        if (RELU_BEFORE_MEAN) r = fmaxf(r, 0.f);
        sum += r;
    }
    out[node * DD + lane] = sum * 0.125f;
}

// ---------------- stream/event resources (created once, pre-capture) ----------
struct HxRes {
    cudaStream_t s2;
    cudaEvent_t e0, e1;
    HxRes() {
        cudaStreamCreateWithFlags(&s2, cudaStreamNonBlocking);
        cudaEventCreateWithFlags(&e0, cudaEventDisableTiming);
        cudaEventCreateWithFlags(&e1, cudaEventDisableTiming);
    }
};
static HxRes& hx() { static HxRes r; return r; }

// ---------------- launcher -----------------------------------------------------
extern "C" void kernel_launch(void* const* d_in, const int* in_sizes, int n_in,
                              void* d_out, int out_size) {
    const float* x   = (const float*)d_in[0];
    const int*   src = (const int*)d_in[1];
    const int*   dst = (const int*)d_in[2];
    const float* W1  = (const float*)d_in[3];
    const float* al1 = (const float*)d_in[4];
    const float* ar1 = (const float*)d_in[5];
    const float* b1  = (const float*)d_in[6];
    const float* W2  = (const float*)d_in[7];
    const float* al2 = (const float*)d_in[8];
    const float* ar2 = (const float*)d_in[9];
    const float* b2  = (const float*)d_in[10];
    float* out = (float*)d_out;

    float *hbuf, *Wp1, *Wp2, *alp1, *arp1, *alp2, *arp2;
    cudaGetSymbolAddress((void**)&hbuf, g_h);
    cudaGetSymbolAddress((void**)&Wp1, g_Wp1);
    cudaGetSymbolAddress((void**)&Wp2, g_Wp2);
    cudaGetSymbolAddress((void**)&alp1, g_alp1);
    cudaGetSymbolAddress((void**)&arp1, g_arp1);
    cudaGetSymbolAddress((void**)&alp2, g_alp2);
    cudaGetSymbolAddress((void**)&arp2, g_arp2);

    const int NTB = (NN + TRB - 1) / TRB;  // 313 tiles
    constexpr int smem1 = (64 * 264 + 64 * 132) * sizeof(float);   // 101376
    constexpr int smem2 = (64 * 260) * sizeof(float);              // 66560
    cudaFuncSetAttribute(gemm_tc_kernel<F1>,
                         cudaFuncAttributeMaxDynamicSharedMemorySize, smem1);
    cudaFuncSetAttribute(gemm_tc_kernel<DD>,
                         cudaFuncAttributeMaxDynamicSharedMemorySize, smem2);

    HxRes& R = hx();

    // fork: CSR chain on s2, overlapped with perm + gemm1
    cudaEventRecord(R.e0, 0);
    cudaStreamWaitEvent(R.s2, R.e0, 0);
    hist_kernel<<<(EE + 255) / 256, 256, 0, R.s2>>>(dst);
    scan_kernel<<<1, 1024, 0, R.s2>>>();
    scatter_kernel<<<(EE + 255) / 256, 256, 0, R.s2>>>(src, dst);
    cudaEventRecord(R.e1, R.s2);

    // main stream: perm, then layer-1 GEMM (+fused el/er, fp16 feat)
    perm_kernel<<<(F1 * HD + 255) / 256, 256>>>(W1, al1, ar1, W2, al2, ar2);
    gemm_tc_kernel<F1><<<NTB, 256, smem1>>>(x, Wp1, alp1, arp1, NN);

    // join, then aggregate layer 1
    cudaStreamWaitEvent(0, R.e1, 0);
    agg_kernel<true><<<(NN + 7) / 8, 256>>>(b1, hbuf);

    // layer 2
    gemm_tc_kernel<DD><<<NTB, 256, smem2>>>(hbuf, Wp2, alp2, arp2, NN);
    agg_kernel<false><<<(NN + 7) / 8, 256>>>(b2, out);
}

// round 11
// speedup vs baseline: 1.4788x; 1.0493x over previous
#include <cuda_runtime.h>
#include <cuda_fp16.h>
#include <cuda_bf16.h>

#define NN 20000
#define EE 320000
#define HH 8
#define DD 32
#define F1 128
#define HD 256   // H*D
#define TRB 64   // gemm row tile

// ---------------- scratch (device globals; no allocation allowed) -------------
__device__ __half g_feat[NN * HD];     // [N, dim*8+head] fp16 features
__device__ float g_el[NN * HH];
__device__ float g_er[NN * HH];
__device__ float g_h[NN * DD];         // layer-1 output (fp32)
__device__ __half g_Wp1h[F1 * HD];     // permuted weights, n-major [col][k], fp16
__device__ __half g_Wp2h[DD * HD];
__device__ float g_alp1[HD], g_arp1[HD];
__device__ float g_alp2[HD], g_arp2[HD];
__device__ int   g_cnt[NN];            // INVARIANT: zero on entry to every call
__device__ int   g_rowptr[NN + 1];
__device__ int   g_fill[NN];
__device__ int   g_esrc[EE];

__device__ __forceinline__ void mma_f16(float& d0, float& d1, float& d2, float& d3,
                                        unsigned a0, unsigned a1, unsigned a2, unsigned a3,
                                        unsigned b0, unsigned b1) {
    asm volatile("mma.sync.aligned.m16n8k16.row.col.f32.f16.f16.f32 "
                 "{%0,%1,%2,%3}, {%4,%5,%6,%7}, {%8,%9}, {%0,%1,%2,%3};"
                 : "+f"(d0), "+f"(d1), "+f"(d2), "+f"(d3)
                 : "r"(a0), "r"(a1), "r"(a2), "r"(a3), "r"(b0), "r"(b1));
}

// ---------------- weight permutation + fp16 conversion (n-major output) -------
// Permuted col j holds logical col L(j) = ((j&7)<<5)|(j>>3) (dim*8+head order).
// Output layout: Wp[j*K + k] (n-major, k contiguous) for .col B-fragment loads.
__global__ void perm_kernel(const float* __restrict__ W1,
                            const float* __restrict__ al1,
                            const float* __restrict__ ar1,
                            const float* __restrict__ W2,
                            const float* __restrict__ al2,
                            const float* __restrict__ ar2) {
    int t = blockIdx.x * 256 + threadIdx.x;
    if (t < F1 * HD) {
        int j = t / F1, k = t % F1;
        int L = ((j & 7) << 5) | (j >> 3);
        g_Wp1h[t] = __float2half_rn(W1[k * HD + L]);
    }
    if (t < DD * HD) {
        int j = t / DD, k = t % DD;
        int L = ((j & 7) << 5) | (j >> 3);
        g_Wp2h[t] = __float2half_rn(W2[k * HD + L]);
    }
    if (t < HD) {
        int L = ((t & 7) << 5) | (t >> 3);
        g_alp1[t] = al1[L]; g_arp1[t] = ar1[L];
        g_alp2[t] = al2[L]; g_arp2[t] = ar2[L];
    }
}

// ---------------- CSR chain (runs on forked stream) ---------------------------
__global__ void hist_kernel(const int* __restrict__ dst) {
    int e = blockIdx.x * blockDim.x + threadIdx.x;
    if (e < EE) atomicAdd(&g_cnt[dst[e]], 1);
}

__global__ void scan_kernel() {   // also restores g_cnt = 0 invariant
    __shared__ int ssum[1024];
    int t = threadIdx.x;
    const int chunk = (NN + 1023) / 1024;
    int b = t * chunk, e = min(b + chunk, NN);
    int s = 0;
    for (int i = b; i < e; i++) s += g_cnt[i];
    ssum[t] = s;
    __syncthreads();
    for (int off = 1; off < 1024; off <<= 1) {
        int v = (t >= off) ? ssum[t - off] : 0;
        __syncthreads();
        ssum[t] += v;
        __syncthreads();
    }
    int pref = (t > 0) ? ssum[t - 1] : 0;
    for (int i = b; i < e; i++) {
        int c = g_cnt[i];
        g_rowptr[i] = pref;
        g_fill[i]   = pref;
        g_cnt[i]    = 0;
        pref += c;
    }
    if (t == 1023) g_rowptr[NN] = ssum[1023];
}

__global__ void scatter_kernel(const int* __restrict__ src,
                               const int* __restrict__ dst) {
    int e = blockIdx.x * blockDim.x + threadIdx.x;
    if (e < EE) {
        int p = atomicAdd(&g_fill[dst[e]], 1);
        g_esrc[p] = src[e];
    }
}

// ---------------- fp16 tensor-core GEMM + fused el/er + fp16 feat -------------
// 256 threads = 8 warps (2 Mgroups x 4 Ngroups). Tile 64 rows x 256 cols.
// mma.m16n8k16 f16: warp = 32 rows (2 m-tiles) x 64 cols (8 n-tiles).
template <int K>
__global__ __launch_bounds__(256, 2) void gemm_tc_kernel(const float* __restrict__ X,
                                                         const __half* __restrict__ Wp,
                                                         const float* __restrict__ alp,
                                                         const float* __restrict__ arp,
                                                         int n) {
    constexpr int KP = K + 8;               // half-row pad: stride ≡ 4 banks mod 32
    constexpr int STP = 260;                // fp32 stage row pad
    extern __shared__ float sh[];
    __half* Wsh = (__half*)sh;              // [HD][KP] n-major
    __half* Xsh = (__half*)sh + HD * KP;    // [TRB][KP] k contiguous
    int tid = threadIdx.x;
    int wid = tid >> 5, lane = tid & 31;
    int g = lane >> 2, tg = lane & 3;
    int warpM = wid >> 2, warpN = wid & 3;
    int nbase = warpN * 64;

    int r0 = blockIdx.x * TRB;
    int nr = min(TRB, n - r0);

    // W -> smem (half2 coalesced)
    for (int idx = tid; idx < HD * (K / 2); idx += 256) {
        int j = idx / (K / 2), k2 = idx % (K / 2);
        *(__half2*)(Wsh + j * KP + 2 * k2) = *(const __half2*)(Wp + j * K + 2 * k2);
    }
    // X -> smem as fp16 (zero pad tail rows)
    for (int idx = tid; idx < TRB * (K / 2); idx += 256) {
        int r = idx / (K / 2), c2 = idx % (K / 2);
        float2 xv = (r < nr) ? *(const float2*)(X + (size_t)(r0 + r) * K + 2 * c2)
                             : make_float2(0.f, 0.f);
        *(__half2*)(Xsh + r * KP + 2 * c2) = __float22half2_rn(xv);
    }
    __syncthreads();

    float acc[2][8][4];
#pragma unroll
    for (int m = 0; m < 2; m++)
#pragma unroll
        for (int t = 0; t < 8; t++)
#pragma unroll
            for (int c = 0; c < 4; c++) acc[m][t][c] = 0.f;

#pragma unroll
    for (int kk = 0; kk < K; kk += 16) {
        unsigned a[2][4];
#pragma unroll
        for (int m = 0; m < 2; m++) {
            int rb = warpM * 32 + m * 16;
            a[m][0] = *(const unsigned*)(Xsh + (rb + g) * KP + kk + 2 * tg);
            a[m][1] = *(const unsigned*)(Xsh + (rb + g + 8) * KP + kk + 2 * tg);
            a[m][2] = *(const unsigned*)(Xsh + (rb + g) * KP + kk + 2 * tg + 8);
            a[m][3] = *(const unsigned*)(Xsh + (rb + g + 8) * KP + kk + 2 * tg + 8);
        }
#pragma unroll
        for (int t = 0; t < 8; t++) {
            int ncol = nbase + t * 8 + g;
            unsigned b0 = *(const unsigned*)(Wsh + ncol * KP + kk + 2 * tg);
            unsigned b1 = *(const unsigned*)(Wsh + ncol * KP + kk + 2 * tg + 8);
            mma_f16(acc[0][t][0], acc[0][t][1], acc[0][t][2], acc[0][t][3],
                    a[0][0], a[0][1], a[0][2], a[0][3], b0, b1);
            mma_f16(acc[1][t][0], acc[1][t][1], acc[1][t][2], acc[1][t][3],
                    a[1][0], a[1][1], a[1][2], a[1][3], b0, b1);
        }
    }

    // stage fp32 result to smem (reuse W/X space)
    __syncthreads();
    float* stage = sh;          // [TRB][STP]
#pragma unroll
    for (int m = 0; m < 2; m++) {
        int rb = warpM * 32 + m * 16;
#pragma unroll
        for (int t = 0; t < 8; t++) {
            int c = nbase + t * 8 + 2 * tg;
            *(float2*)&stage[(rb + g) * STP + c] =
                make_float2(acc[m][t][0], acc[m][t][1]);
            *(float2*)&stage[(rb + g + 8) * STP + c] =
                make_float2(acc[m][t][2], acc[m][t][3]);
        }
    }
    __syncthreads();

    // fp16 feat writeout (coalesced)
    for (int i = tid; i < nr * 32; i += 256) {
        int row = i >> 5, cg = i & 31;
        const float4* s4 = (const float4*)&stage[row * STP + cg * 8];
        float4 f0 = s4[0], f1 = s4[1];
        __half2 h0 = __floats2half2_rn(f0.x, f0.y);
        __half2 h1 = __floats2half2_rn(f0.z, f0.w);
        __half2 h2 = __floats2half2_rn(f1.x, f1.y);
        __half2 h3 = __floats2half2_rn(f1.z, f1.w);
        uint4 u = make_uint4(*(unsigned*)&h0, *(unsigned*)&h1,
                             *(unsigned*)&h2, *(unsigned*)&h3);
        *(uint4*)(&g_feat[(size_t)(r0 + row) * HD + cg * 8]) = u;
    }

    // el/er: warp per row
    float av[8], bv[8];
    {
        const float4* ap = (const float4*)(alp + lane * 8);
        const float4* bp = (const float4*)(arp + lane * 8);
        float4 a0 = ap[0], a1 = ap[1], b0 = bp[0], b1 = bp[1];
        av[0]=a0.x; av[1]=a0.y; av[2]=a0.z; av[3]=a0.w;
        av[4]=a1.x; av[5]=a1.y; av[6]=a1.z; av[7]=a1.w;
        bv[0]=b0.x; bv[1]=b0.y; bv[2]=b0.z; bv[3]=b0.w;
        bv[4]=b1.x; bv[5]=b1.y; bv[6]=b1.z; bv[7]=b1.w;
    }
    for (int row = wid; row < nr; row += 8) {
        const float4* f4 = (const float4*)(stage + row * STP + lane * 8);
        float4 f0 = f4[0], f1 = f4[1];
        float pa[8] = {f0.x*av[0], f0.y*av[1], f0.z*av[2], f0.w*av[3],
                       f1.x*av[4], f1.y*av[5], f1.z*av[6], f1.w*av[7]};
        float pb[8] = {f0.x*bv[0], f0.y*bv[1], f0.z*bv[2], f0.w*bv[3],
                       f1.x*bv[4], f1.y*bv[5], f1.z*bv[6], f1.w*bv[7]};
#pragma unroll
        for (int h = 0; h < 8; h++) {
#pragma unroll
            for (int off = 16; off; off >>= 1) {
                pa[h] += __shfl_xor_sync(0xffffffffu, pa[h], off);
                pb[h] += __shfl_xor_sync(0xffffffffu, pb[h], off);
            }
        }
        if (lane == 0) {
            float* elp = g_el + (size_t)(r0 + row) * HH;
            float* erp = g_er + (size_t)(r0 + row) * HH;
            *(float4*)(elp)     = make_float4(pa[0], pa[1], pa[2], pa[3]);
            *(float4*)(elp + 4) = make_float4(pa[4], pa[5], pa[6], pa[7]);
            *(float4*)(erp)     = make_float4(pb[0], pb[1], pb[2], pb[3]);
            *(float4*)(erp + 4) = make_float4(pb[4], pb[5], pb[6], pb[7]);
        }
    }
}

// ---------------- aggregation (warp per dst node, unroll x4, fp16 feat) -------
template <bool RELU_BEFORE_MEAN>
__global__ void agg_kernel(const float* __restrict__ bias,
                           float* __restrict__ out) {
    int node = blockIdx.x * (blockDim.x >> 5) + (threadIdx.x >> 5);
    if (node >= NN) return;
    int lane = threadIdx.x & 31;
    int hh = lane & 7;
    float er_l = g_er[node * HH + hh];
    int beg = g_rowptr[node], end = g_rowptr[node + 1];

    float acc[8];
#pragma unroll
    for (int h = 0; h < 8; h++) acc[h] = 0.f;
    float den_l = 0.f;

    int i = beg;
    for (; i + 4 <= end; i += 4) {
        int s0 = g_esrc[i + 0], s1 = g_esrc[i + 1];
        int s2 = g_esrc[i + 2], s3 = g_esrc[i + 3];
        float el0 = __ldg(g_el + s0 * HH + hh);
        float el1 = __ldg(g_el + s1 * HH + hh);
        float el2 = __ldg(g_el + s2 * HH + hh);
        float el3 = __ldg(g_el + s3 * HH + hh);
        uint4 u0 = *(const uint4*)(&g_feat[(size_t)s0 * HD + lane * 8]);
        uint4 u1 = *(const uint4*)(&g_feat[(size_t)s1 * HD + lane * 8]);
        uint4 u2 = *(const uint4*)(&g_feat[(size_t)s2 * HD + lane * 8]);
        uint4 u3 = *(const uint4*)(&g_feat[(size_t)s3 * HD + lane * 8]);
        float v0 = el0 + er_l; v0 = v0 > 0.f ? v0 : 0.2f * v0;
        float v1 = el1 + er_l; v1 = v1 > 0.f ? v1 : 0.2f * v1;
        float v2 = el2 + er_l; v2 = v2 > 0.f ? v2 : 0.2f * v2;
        float v3 = el3 + er_l; v3 = v3 > 0.f ? v3 : 0.2f * v3;
        float e0 = __expf(v0), e1 = __expf(v1);
        float e2 = __expf(v2), e3 = __expf(v3);
        den_l += (e0 + e1) + (e2 + e3);
        const unsigned* p0 = &u0.x;
        const unsigned* p1 = &u1.x;
        const unsigned* p2 = &u2.x;
        const unsigned* p3 = &u3.x;
#pragma unroll
        for (int q = 0; q < 4; q++) {       // q = head pair (2q, 2q+1)
            float2 f0 = __half22float2(*(const __half2*)&p0[q]);
            float2 f1 = __half22float2(*(const __half2*)&p1[q]);
            float2 f2 = __half22float2(*(const __half2*)&p2[q]);
            float2 f3 = __half22float2(*(const __half2*)&p3[q]);
            float wa0 = __shfl_sync(0xffffffffu, e0, 2 * q);
            float wa1 = __shfl_sync(0xffffffffu, e0, 2 * q + 1);
            float wb0 = __shfl_sync(0xffffffffu, e1, 2 * q);
            float wb1 = __shfl_sync(0xffffffffu, e1, 2 * q + 1);
            float wc0 = __shfl_sync(0xffffffffu, e2, 2 * q);
            float wc1 = __shfl_sync(0xffffffffu, e2, 2 * q + 1);
            float wd0 = __shfl_sync(0xffffffffu, e3, 2 * q);
            float wd1 = __shfl_sync(0xffffffffu, e3, 2 * q + 1);
            acc[2 * q]     = fmaf(wa0, f0.x, acc[2 * q]);
            acc[2 * q + 1] = fmaf(wa1, f0.y, acc[2 * q + 1]);
            acc[2 * q]     = fmaf(wb0, f1.x, acc[2 * q]);
            acc[2 * q + 1] = fmaf(wb1, f1.y, acc[2 * q + 1]);
            acc[2 * q]     = fmaf(wc0, f2.x, acc[2 * q]);
            acc[2 * q + 1] = fmaf(wc1, f2.y, acc[2 * q + 1]);
            acc[2 * q]     = fmaf(wd0, f3.x, acc[2 * q]);
            acc[2 * q + 1] = fmaf(wd1, f3.y, acc[2 * q + 1]);
        }
    }
    for (; i < end; i++) {
        int s = g_esrc[i];
        float elv = __ldg(g_el + s * HH + hh);
        uint4 u0 = *(const uint4*)(&g_feat[(size_t)s * HD + lane * 8]);
        float v = elv + er_l; v = v > 0.f ? v : 0.2f * v;
        float e = __expf(v);
        den_l += e;
        const unsigned* p0 = &u0.x;
#pragma unroll
        for (int q = 0; q < 4; q++) {
            float2 f0 = __half22float2(*(const __half2*)&p0[q]);
            float w0 = __shfl_sync(0xffffffffu, e, 2 * q);
            float w1 = __shfl_sync(0xffffffffu, e, 2 * q + 1);
            acc[2 * q]     = fmaf(w0, f0.x, acc[2 * q]);
            acc[2 * q + 1] = fmaf(w1, f0.y, acc[2 * q + 1]);
        }
    }

    float sum = 0.f;
#pragma unroll
    for (int h = 0; h < 8; h++) {
        float dh = __shfl_sync(0xffffffffu, den_l, h);
        float r = (dh > 0.f) ? __fdividef(acc[h], dh) : 0.f;
        r += bias[h * DD + lane];
        if (RELU_BEFORE_MEAN) r = fmaxf(r, 0.f);
        sum += r;
    }
    out[node * DD + lane] = sum * 0.125f;
}

// ---------------- stream/event resources (created once, pre-capture) ----------
struct HxRes {
    cudaStream_t s2;
    cudaEvent_t e0, e1;
    HxRes() {
        cudaStreamCreateWithFlags(&s2, cudaStreamNonBlocking);
        cudaEventCreateWithFlags(&e0, cudaEventDisableTiming);
        cudaEventCreateWithFlags(&e1, cudaEventDisableTiming);
    }
};
static HxRes& hx() { static HxRes r; return r; }

// ---------------- launcher -----------------------------------------------------
extern "C" void kernel_launch(void* const* d_in, const int* in_sizes, int n_in,
                              void* d_out, int out_size) {
    const float* x   = (const float*)d_in[0];
    const int*   src = (const int*)d_in[1];
    const int*   dst = (const int*)d_in[2];
    const float* W1  = (const float*)d_in[3];
    const float* al1 = (const float*)d_in[4];
    const float* ar1 = (const float*)d_in[5];
    const float* b1  = (const float*)d_in[6];
    const float* W2  = (const float*)d_in[7];
    const float* al2 = (const float*)d_in[8];
    const float* ar2 = (const float*)d_in[9];
    const float* b2  = (const float*)d_in[10];
    float* out = (float*)d_out;

    float *hbuf, *alp1, *arp1, *alp2, *arp2;
    __half *Wp1, *Wp2;
    cudaGetSymbolAddress((void**)&hbuf, g_h);
    cudaGetSymbolAddress((void**)&Wp1, g_Wp1h);
    cudaGetSymbolAddress((void**)&Wp2, g_Wp2h);
    cudaGetSymbolAddress((void**)&alp1, g_alp1);
    cudaGetSymbolAddress((void**)&arp1, g_arp1);
    cudaGetSymbolAddress((void**)&alp2, g_alp2);
    cudaGetSymbolAddress((void**)&arp2, g_arp2);

    const int NTB = (NN + TRB - 1) / TRB;  // 313 tiles
    // smem1: W 256*136*2 + X 64*136*2 = 87040; stage 64*260*4 = 66560 (fits)
    // smem2: max(25600, 66560) = 66560
    constexpr int smem1 = (HD * (F1 + 8) + TRB * (F1 + 8)) * 2;
    constexpr int smem2 = TRB * 260 * 4;
    cudaFuncSetAttribute(gemm_tc_kernel<F1>,
                         cudaFuncAttributeMaxDynamicSharedMemorySize, smem1);
    cudaFuncSetAttribute(gemm_tc_kernel<DD>,
                         cudaFuncAttributeMaxDynamicSharedMemorySize, smem2);

    HxRes& R = hx();

    // fork: CSR chain on s2, overlapped with perm + gemm1
    cudaEventRecord(R.e0, 0);
    cudaStreamWaitEvent(R.s2, R.e0, 0);
    hist_kernel<<<(EE + 255) / 256, 256, 0, R.s2>>>(dst);
    scan_kernel<<<1, 1024, 0, R.s2>>>();
    scatter_kernel<<<(EE + 255) / 256, 256, 0, R.s2>>>(src, dst);
    cudaEventRecord(R.e1, R.s2);

    // main stream: perm, then layer-1 GEMM (+fused el/er, fp16 feat)
    perm_kernel<<<(F1 * HD + 255) / 256, 256>>>(W1, al1, ar1, W2, al2, ar2);
    gemm_tc_kernel<F1><<<NTB, 256, smem1>>>(x, Wp1, alp1, arp1, NN);

    // join, then aggregate layer 1
    cudaStreamWaitEvent(0, R.e1, 0);
    agg_kernel<true><<<(NN + 7) / 8, 256>>>(b1, hbuf);

    // layer 2
    gemm_tc_kernel<DD><<<NTB, 256, smem2>>>(hbuf, Wp2, alp2, arp2, NN);
    agg_kernel<false><<<(NN + 7) / 8, 256>>>(b2, out);
}